// round 1
// baseline (speedup 1.0000x reference)
#include <cuda_runtime.h>
#include <math.h>

// Problem constants
#define B_    128
#define D_    2048
#define C_    16522
#define CP    16544          // padded row stride for logits scratch (multiple of 16)
#define KNN_  6

static __device__ float g_logits[B_ * CP];   // ~8.47 MB scratch
static __device__ float g_rowloss[B_];

// ---------------------------------------------------------------------------
// Kernel 1: copy em -> out[1..] (em_new base copy; updated rows overwritten later)
// ---------------------------------------------------------------------------
__global__ void copy_kernel(const float* __restrict__ em, float* __restrict__ out) {
    long long n = (long long)C_ * D_;
    long long stride = (long long)gridDim.x * blockDim.x;
    for (long long i = (long long)blockIdx.x * blockDim.x + threadIdx.x; i < n; i += stride)
        out[1 + i] = em[i];
}

// ---------------------------------------------------------------------------
// Kernel 2: tiled fp32 SGEMM  logits[b][c] = dot(X[b], Em[c]) * 20
// Block computes 128(B) x 128(C) tile. 256 threads, 8x8 micro-tile each.
// ---------------------------------------------------------------------------
__global__ __launch_bounds__(256) void gemm_kernel(const float* __restrict__ A,
                                                   const float* __restrict__ Em) {
    const int c0  = blockIdx.x * 128;
    const int tid = threadIdx.x;
    const int tx  = tid & 15;        // c-tile coordinate (x8)
    const int ty  = tid >> 4;        // b coordinate (x8)

    __shared__ float As[16][128];
    __shared__ float Bs[16][128];

    float acc[8][8];
    #pragma unroll
    for (int i = 0; i < 8; i++)
        #pragma unroll
        for (int j = 0; j < 8; j++) acc[i][j] = 0.f;

    const int l0 = tid * 2;   // each thread loads 2 float4 per tile per matrix

    for (int k0 = 0; k0 < D_; k0 += 16) {
        #pragma unroll
        for (int t = 0; t < 2; t++) {
            int l   = l0 + t;
            int row = l >> 2;            // 0..127
            int kq  = (l & 3) << 2;      // 0,4,8,12
            float4 f = *(const float4*)&A[row * D_ + k0 + kq];
            As[kq + 0][row] = f.x; As[kq + 1][row] = f.y;
            As[kq + 2][row] = f.z; As[kq + 3][row] = f.w;
            int c = c0 + row;
            float4 g = make_float4(0.f, 0.f, 0.f, 0.f);
            if (c < C_) g = *(const float4*)&Em[(long long)c * D_ + k0 + kq];
            Bs[kq + 0][row] = g.x; Bs[kq + 1][row] = g.y;
            Bs[kq + 2][row] = g.z; Bs[kq + 3][row] = g.w;
        }
        __syncthreads();

        #pragma unroll
        for (int k = 0; k < 16; k++) {
            float a[8], b[8];
            *(float4*)&a[0] = *(const float4*)&As[k][ty * 8];
            *(float4*)&a[4] = *(const float4*)&As[k][ty * 8 + 4];
            *(float4*)&b[0] = *(const float4*)&Bs[k][tx * 8];
            *(float4*)&b[4] = *(const float4*)&Bs[k][tx * 8 + 4];
            #pragma unroll
            for (int i = 0; i < 8; i++)
                #pragma unroll
                for (int j = 0; j < 8; j++)
                    acc[i][j] = fmaf(a[i], b[j], acc[i][j]);
        }
        __syncthreads();
    }

    #pragma unroll
    for (int i = 0; i < 8; i++) {
        int b = ty * 8 + i;
        #pragma unroll
        for (int j = 0; j < 8; j++) {
            int c = c0 + tx * 8 + j;
            if (c < C_) g_logits[b * CP + c] = acc[i][j] * 20.0f;  // 1/BETA
        }
    }
}

// ---------------------------------------------------------------------------
// Kernel 3: per-row logsumexp + top-6 + row loss. One block per B-row.
// ---------------------------------------------------------------------------
__global__ __launch_bounds__(256) void row_reduce_kernel(const int* __restrict__ label) {
    const int b   = blockIdx.x;
    const int tid = threadIdx.x;
    const float* row = &g_logits[b * CP];

    float m = -INFINITY, s = 0.f;
    float tv[KNN_];
    int   ti[KNN_];
    #pragma unroll
    for (int j = 0; j < KNN_; j++) { tv[j] = -INFINITY; ti[j] = -1; }

    for (int c = tid; c < C_; c += 256) {
        float v = row[c];
        if (v > m) { s = s * __expf(m - v) + 1.f; m = v; }
        else       { s += __expf(v - m); }
        if (v > tv[KNN_ - 1]) {
            int p = KNN_ - 1;
            while (p > 0 && v > tv[p - 1]) { tv[p] = tv[p - 1]; ti[p] = ti[p - 1]; p--; }
            tv[p] = v; ti[p] = c;
        }
    }

    __shared__ float sm[256], ss[256];
    __shared__ float cv[256 * KNN_];
    __shared__ int   ci[256 * KNN_];
    __shared__ float rv[256];
    __shared__ int   ri[256];
    __shared__ float out_tv[KNN_];
    __shared__ int   out_ti[KNN_];

    sm[tid] = m; ss[tid] = s;
    #pragma unroll
    for (int j = 0; j < KNN_; j++) { cv[tid * KNN_ + j] = tv[j]; ci[tid * KNN_ + j] = ti[j]; }
    __syncthreads();

    // logsumexp tree reduce
    for (int off = 128; off > 0; off >>= 1) {
        if (tid < off) {
            float m2 = sm[tid + off], s2 = ss[tid + off];
            float m1 = sm[tid],       s1 = ss[tid];
            float mm = fmaxf(m1, m2);
            ss[tid] = s1 * __expf(m1 - mm) + s2 * __expf(m2 - mm);
            sm[tid] = mm;
        }
        __syncthreads();
    }

    // 6 rounds of global arg-max over all thread-local top-6 candidates
    for (int r = 0; r < KNN_; r++) {
        float bm = -INFINITY; int bi = -1;
        #pragma unroll
        for (int j = 0; j < KNN_; j++) {
            float v = cv[tid * KNN_ + j];
            if (v > bm) { bm = v; bi = tid * KNN_ + j; }
        }
        rv[tid] = bm; ri[tid] = bi;
        __syncthreads();
        for (int off = 128; off > 0; off >>= 1) {
            if (tid < off && rv[tid + off] > rv[tid]) {
                rv[tid] = rv[tid + off]; ri[tid] = ri[tid + off];
            }
            __syncthreads();
        }
        if (tid == 0) {
            out_tv[r] = rv[0];
            out_ti[r] = ci[ri[0]];
            cv[ri[0]] = -INFINITY;
        }
        __syncthreads();
    }

    if (tid == 0) {
        float LSE  = sm[0] + logf(ss[0]);
        int   y    = label[b];
        float vlab = row[y];
        float sum2 = 0.f;
        int   in   = 0;
        #pragma unroll
        for (int j = 0; j < KNN_; j++) {
            sum2 += (LSE - out_tv[j]);
            if (out_ti[j] == y) in = 1;
        }
        float ll = LSE - vlab;   // -logp[label]
        g_rowloss[b] = 2.f * sum2 + (3.f - 2.f * (float)in) * ll;
    }
}

// ---------------------------------------------------------------------------
// Kernel 4: deterministic mean of row losses -> out[0]
// ---------------------------------------------------------------------------
__global__ void finalize_loss(float* __restrict__ out) {
    __shared__ float sh[128];
    int t = threadIdx.x;
    sh[t] = g_rowloss[t];
    __syncthreads();
    for (int off = 64; off > 0; off >>= 1) {
        if (t < off) sh[t] += sh[t + off];
        __syncthreads();
    }
    if (t == 0) out[0] = sh[0] / (float)B_;
}

// ---------------------------------------------------------------------------
// Kernel 5: EMA memory-bank update. One block per sample; only chain heads run,
// processing their whole duplicate-label chain with the row held in registers.
// ---------------------------------------------------------------------------
__global__ __launch_bounds__(256) void update_kernel(const float* __restrict__ X,
                                                     const int* __restrict__ label,
                                                     const float* __restrict__ em,
                                                     float* __restrict__ em_out,
                                                     const int* __restrict__ epoch_p) {
    const int b = blockIdx.x;
    const int y = label[b];
    for (int j = 0; j < b; j++)
        if (label[j] == y) return;          // not a chain head

    const float alpha = 0.01f * (float)epoch_p[0];
    const int tid = threadIdx.x;
    const int lane = tid & 31, wid = tid >> 5;

    float r[8];
    #pragma unroll
    for (int k = 0; k < 8; k++) r[k] = em[(long long)y * D_ + k * 256 + tid];

    __shared__ float red[8];

    for (int i = b; i < B_; i++) {
        if (label[i] != y) continue;
        float sq = 0.f;
        #pragma unroll
        for (int k = 0; k < 8; k++) {
            r[k] = alpha * r[k] + (1.f - alpha) * X[i * D_ + k * 256 + tid];
            sq = fmaf(r[k], r[k], sq);
        }
        #pragma unroll
        for (int o = 16; o > 0; o >>= 1) sq += __shfl_xor_sync(0xffffffffu, sq, o);
        if (lane == 0) red[wid] = sq;
        __syncthreads();
        float tot;
        if (tid == 0) {
            tot = 0.f;
            #pragma unroll
            for (int w = 0; w < 8; w++) tot += red[w];
            red[0] = tot;
        }
        __syncthreads();
        float inv = 1.f / sqrtf(red[0]);
        __syncthreads();                     // protect red[] before next iteration
        #pragma unroll
        for (int k = 0; k < 8; k++) r[k] *= inv;
    }

    #pragma unroll
    for (int k = 0; k < 8; k++) em_out[(long long)y * D_ + k * 256 + tid] = r[k];
}

// ---------------------------------------------------------------------------
// Launch
// ---------------------------------------------------------------------------
extern "C" void kernel_launch(void* const* d_in, const int* in_sizes, int n_in,
                              void* d_out, int out_size) {
    const float* X     = (const float*)d_in[0];  // [128, 2048] f32
    const int*   label = (const int*)  d_in[1];  // [128] i32
    const float* Em    = (const float*)d_in[2];  // [16522, 2048] f32
    const int*   epoch = (const int*)  d_in[3];  // scalar

    float* out = (float*)d_out;                  // [0]=loss, [1..]=em_new

    copy_kernel      <<<2048, 256>>>(Em, out);
    gemm_kernel      <<<(C_ + 127) / 128, 256>>>(X, Em);
    row_reduce_kernel<<<B_, 256>>>(label);
    finalize_loss    <<<1, 128>>>(out);
    update_kernel    <<<B_, 256>>>(X, label, Em, out + 1, epoch);
}

// round 3
// speedup vs baseline: 1.6711x; 1.6711x over previous
#include <cuda_runtime.h>
#include <cuda_bf16.h>
#include <mma.h>
#include <math.h>
#include <stdint.h>

using namespace nvcuda;

// Problem constants
#define B_    128
#define D_    2048
#define C_    16522
#define CP    16640          // padded logits stride: covers 130*128 tile stores
#define KNN_  6
#define BM    128
#define KC    32             // f32 K-elements per pipeline chunk
#define LDA   40             // KC + 8 bf16 pad (conflict-free ldmatrix)
#define NCHUNK (D_ / KC)     // 64
#define NTILE  130           // ceil(C_/128)

static __device__ float g_logits[B_ * CP];   // ~8.5 MB scratch
static __device__ float g_rowloss[B_];

// SMEM: 2 stages x {Ah, Al, Bh, Bl}, each 128 x LDA bf16 (10240 B) -> 81920 B
struct Smem {
    __nv_bfloat16 Ah[2][BM * LDA];
    __nv_bfloat16 Al[2][BM * LDA];
    __nv_bfloat16 Bh[2][BM * LDA];
    __nv_bfloat16 Bl[2][BM * LDA];
};
#define SMEM_DYN (sizeof(Smem))

// ---------------------------------------------------------------------------
// Fused kernel: bf16-split HMMA GEMM (logits = X·Emᵀ, x20 applied later)
// + fused em -> out copy. One CTA per 128-row em tile.
// A = em tile (M=128 rows), B = X (N=128 batch), K = 2048.
// ---------------------------------------------------------------------------
__global__ __launch_bounds__(256, 1) void gemm_fused(const float* __restrict__ X,
                                                     const float* __restrict__ Em,
                                                     float* __restrict__ out1) {
    extern __shared__ char smraw[];
    Smem* sm = (Smem*)smraw;

    const int tid = threadIdx.x;
    const int wid = tid >> 5;
    const int c0  = blockIdx.x * BM;
    const int wm  = (wid & 3) * 32;   // warp M origin (em rows)
    const int wn  = (wid >> 2) * 64;  // warp N origin (batch)

    wmma::fragment<wmma::accumulator, 16, 16, 16, float> acc[2][4];
    #pragma unroll
    for (int i = 0; i < 2; i++)
        #pragma unroll
        for (int j = 0; j < 4; j++) wmma::fill_fragment(acc[i][j], 0.0f);

    float4 pf[8];   // prefetch registers: 8 float4 = 32 f32 per thread per chunk

    // global -> registers for one K-chunk (A tile rows + X rows)
    auto ldchunk = [&](int chunk) {
        const int k0 = chunk * KC;
        #pragma unroll
        for (int t = 0; t < 8; t++) {
            const int g   = tid + t * 256;     // 0..2047
            const int mat = g >> 10;           // 0 = A(em), 1 = B(X)
            const int idx = g & 1023;
            const int row = idx >> 3;          // 0..127
            const int q   = idx & 7;           // quad of 4 floats
            if (mat == 0) {
                const int c = c0 + row;
                if (c < C_)
                    pf[t] = *(const float4*)(Em + (long long)c * D_ + k0 + q * 4);
                else
                    pf[t] = make_float4(0.f, 0.f, 0.f, 0.f);
            } else {
                pf[t] = *(const float4*)(X + (long long)row * D_ + k0 + q * 4);
            }
        }
    };

    // registers -> smem (hi/lo bf16 split) + fused em copy to out
    auto stchunk = [&](int chunk, int st) {
        const int k0 = chunk * KC;
        #pragma unroll
        for (int t = 0; t < 8; t++) {
            const int g   = tid + t * 256;
            const int mat = g >> 10;
            const int idx = g & 1023;
            const int row = idx >> 3;
            const int q   = idx & 7;
            float4 f = pf[t];
            __nv_bfloat162 h0 = __float22bfloat162_rn(make_float2(f.x, f.y));
            __nv_bfloat162 l0 = __float22bfloat162_rn(
                make_float2(f.x - __bfloat162float(h0.x), f.y - __bfloat162float(h0.y)));
            __nv_bfloat162 h1 = __float22bfloat162_rn(make_float2(f.z, f.w));
            __nv_bfloat162 l1 = __float22bfloat162_rn(
                make_float2(f.z - __bfloat162float(h1.x), f.w - __bfloat162float(h1.y)));
            __nv_bfloat16* hb = mat ? sm->Bh[st] : sm->Ah[st];
            __nv_bfloat16* lb = mat ? sm->Bl[st] : sm->Al[st];
            const int so = row * LDA + q * 4;
            *(__nv_bfloat162*)(hb + so)     = h0;
            *(__nv_bfloat162*)(hb + so + 2) = h1;
            *(__nv_bfloat162*)(lb + so)     = l0;
            *(__nv_bfloat162*)(lb + so + 2) = l1;
            if (mat == 0 && c0 + row < C_) {   // fused em -> out copy (4B-aligned dst)
                float* o = out1 + (long long)(c0 + row) * D_ + k0 + q * 4;
                o[0] = f.x; o[1] = f.y; o[2] = f.z; o[3] = f.w;
            }
        }
    };

    ldchunk(0);
    stchunk(0, 0);
    __syncthreads();

    for (int s = 0; s < NCHUNK; s++) {
        const int st = s & 1;
        if (s + 1 < NCHUNK) ldchunk(s + 1);   // overlap gmem latency with MMA

        #pragma unroll
        for (int kk = 0; kk < KC; kk += 16) {
            wmma::fragment<wmma::matrix_a, 16, 16, 16, __nv_bfloat16, wmma::row_major> ah[2], al[2];
            wmma::fragment<wmma::matrix_b, 16, 16, 16, __nv_bfloat16, wmma::col_major> bh[4], bl[4];
            #pragma unroll
            for (int i = 0; i < 2; i++) {
                wmma::load_matrix_sync(ah[i], sm->Ah[st] + (wm + i * 16) * LDA + kk, LDA);
                wmma::load_matrix_sync(al[i], sm->Al[st] + (wm + i * 16) * LDA + kk, LDA);
            }
            #pragma unroll
            for (int j = 0; j < 4; j++) {
                wmma::load_matrix_sync(bh[j], sm->Bh[st] + (wn + j * 16) * LDA + kk, LDA);
                wmma::load_matrix_sync(bl[j], sm->Bl[st] + (wn + j * 16) * LDA + kk, LDA);
            }
            #pragma unroll
            for (int i = 0; i < 2; i++)
                #pragma unroll
                for (int j = 0; j < 4; j++) {
                    wmma::mma_sync(acc[i][j], ah[i], bh[j], acc[i][j]);
                    wmma::mma_sync(acc[i][j], ah[i], bl[j], acc[i][j]);
                    wmma::mma_sync(acc[i][j], al[i], bh[j], acc[i][j]);
                }
        }
        __syncthreads();
        if (s + 1 < NCHUNK) {
            stchunk(s + 1, st ^ 1);
            __syncthreads();
        }
    }

    // store: D(m=c-local, n=batch) -> g_logits[n*CP + c0+m] (col-major store)
    #pragma unroll
    for (int i = 0; i < 2; i++)
        #pragma unroll
        for (int j = 0; j < 4; j++) {
            float* p = g_logits + (long long)(wn + j * 16) * CP + c0 + wm + i * 16;
            wmma::store_matrix_sync(p, acc[i][j], CP, wmma::mem_col_major);
        }
}

// ---------------------------------------------------------------------------
// Per-row logsumexp + top-6 + row loss. One block per B-row.
// Logits scale x20 (1/BETA) applied at load.
// ---------------------------------------------------------------------------
__global__ __launch_bounds__(256) void row_reduce_kernel(const int* __restrict__ label) {
    const int b   = blockIdx.x;
    const int tid = threadIdx.x;
    const float* row = &g_logits[b * CP];

    float m = -INFINITY, s = 0.f;
    float tv[KNN_];
    int   ti[KNN_];
    #pragma unroll
    for (int j = 0; j < KNN_; j++) { tv[j] = -INFINITY; ti[j] = -1; }

    for (int c = tid; c < C_; c += 256) {
        float v = row[c] * 20.0f;
        if (v > m) { s = s * __expf(m - v) + 1.f; m = v; }
        else       { s += __expf(v - m); }
        if (v > tv[KNN_ - 1]) {
            int p = KNN_ - 1;
            while (p > 0 && v > tv[p - 1]) { tv[p] = tv[p - 1]; ti[p] = ti[p - 1]; p--; }
            tv[p] = v; ti[p] = c;
        }
    }

    __shared__ float sm[256], ss[256];
    __shared__ float cv[256 * KNN_];
    __shared__ int   ci[256 * KNN_];
    __shared__ float rv[256];
    __shared__ int   ri[256];
    __shared__ float out_tv[KNN_];
    __shared__ int   out_ti[KNN_];

    sm[tid] = m; ss[tid] = s;
    #pragma unroll
    for (int j = 0; j < KNN_; j++) { cv[tid * KNN_ + j] = tv[j]; ci[tid * KNN_ + j] = ti[j]; }
    __syncthreads();

    for (int off = 128; off > 0; off >>= 1) {
        if (tid < off) {
            float m2 = sm[tid + off], s2 = ss[tid + off];
            float m1 = sm[tid],       s1 = ss[tid];
            float mm = fmaxf(m1, m2);
            ss[tid] = s1 * __expf(m1 - mm) + s2 * __expf(m2 - mm);
            sm[tid] = mm;
        }
        __syncthreads();
    }

    for (int r = 0; r < KNN_; r++) {
        float bm = -INFINITY; int bi = -1;
        #pragma unroll
        for (int j = 0; j < KNN_; j++) {
            float v = cv[tid * KNN_ + j];
            if (v > bm) { bm = v; bi = tid * KNN_ + j; }
        }
        rv[tid] = bm; ri[tid] = bi;
        __syncthreads();
        for (int off = 128; off > 0; off >>= 1) {
            if (tid < off && rv[tid + off] > rv[tid]) {
                rv[tid] = rv[tid + off]; ri[tid] = ri[tid + off];
            }
            __syncthreads();
        }
        if (tid == 0) {
            out_tv[r] = rv[0];
            out_ti[r] = ci[ri[0]];
            cv[ri[0]] = -INFINITY;
        }
        __syncthreads();
    }

    if (tid == 0) {
        float LSE  = sm[0] + logf(ss[0]);
        int   y    = label[b];
        float vlab = row[y] * 20.0f;
        float sum2 = 0.f;
        int   in   = 0;
        #pragma unroll
        for (int j = 0; j < KNN_; j++) {
            sum2 += (LSE - out_tv[j]);
            if (out_ti[j] == y) in = 1;
        }
        float ll = LSE - vlab;
        g_rowloss[b] = 2.f * sum2 + (3.f - 2.f * (float)in) * ll;
    }
}

// ---------------------------------------------------------------------------
// Deterministic mean of row losses -> out[0]
// ---------------------------------------------------------------------------
__global__ void finalize_loss(float* __restrict__ out) {
    __shared__ float sh[128];
    int t = threadIdx.x;
    sh[t] = g_rowloss[t];
    __syncthreads();
    for (int off = 64; off > 0; off >>= 1) {
        if (t < off) sh[t] += sh[t + off];
        __syncthreads();
    }
    if (t == 0) out[0] = sh[0] / (float)B_;
}

// ---------------------------------------------------------------------------
// EMA memory-bank update (duplicate-label chains, row held in registers)
// ---------------------------------------------------------------------------
__global__ __launch_bounds__(256) void update_kernel(const float* __restrict__ X,
                                                     const int* __restrict__ label,
                                                     const float* __restrict__ em,
                                                     float* __restrict__ em_out,
                                                     const int* __restrict__ epoch_p) {
    const int b = blockIdx.x;
    const int y = label[b];
    for (int j = 0; j < b; j++)
        if (label[j] == y) return;

    const float alpha = 0.01f * (float)epoch_p[0];
    const int tid = threadIdx.x;
    const int lane = tid & 31, wid = tid >> 5;

    float r[8];
    #pragma unroll
    for (int k = 0; k < 8; k++) r[k] = em[(long long)y * D_ + k * 256 + tid];

    __shared__ float red[8];

    for (int i = b; i < B_; i++) {
        if (label[i] != y) continue;
        float sq = 0.f;
        #pragma unroll
        for (int k = 0; k < 8; k++) {
            r[k] = alpha * r[k] + (1.f - alpha) * X[i * D_ + k * 256 + tid];
            sq = fmaf(r[k], r[k], sq);
        }
        #pragma unroll
        for (int o = 16; o > 0; o >>= 1) sq += __shfl_xor_sync(0xffffffffu, sq, o);
        if (lane == 0) red[wid] = sq;
        __syncthreads();
        if (tid == 0) {
            float tot = 0.f;
            #pragma unroll
            for (int w = 0; w < 8; w++) tot += red[w];
            red[0] = tot;
        }
        __syncthreads();
        float inv = 1.f / sqrtf(red[0]);
        __syncthreads();
        #pragma unroll
        for (int k = 0; k < 8; k++) r[k] *= inv;
    }

    #pragma unroll
    for (int k = 0; k < 8; k++) em_out[(long long)y * D_ + k * 256 + tid] = r[k];
}

// ---------------------------------------------------------------------------
// Launch
// ---------------------------------------------------------------------------
extern "C" void kernel_launch(void* const* d_in, const int* in_sizes, int n_in,
                              void* d_out, int out_size) {
    const float* X     = (const float*)d_in[0];  // [128, 2048] f32
    const int*   label = (const int*)  d_in[1];  // [128] i32
    const float* Em    = (const float*)d_in[2];  // [16522, 2048] f32
    const int*   epoch = (const int*)  d_in[3];  // scalar

    float* out = (float*)d_out;                  // [0]=loss, [1..]=em_new

    cudaFuncSetAttribute(gemm_fused, cudaFuncAttributeMaxDynamicSharedMemorySize, SMEM_DYN);

    gemm_fused       <<<NTILE, 256, SMEM_DYN>>>(X, Em, out + 1);
    row_reduce_kernel<<<B_, 256>>>(label);
    finalize_loss    <<<1, 128>>>(out);
    update_kernel    <<<B_, 256>>>(X, label, Em, out + 1, epoch);
}

// round 4
// speedup vs baseline: 2.7289x; 1.6330x over previous
#include <cuda_runtime.h>
#include <cuda_fp16.h>
#include <mma.h>
#include <math.h>
#include <stdint.h>

using namespace nvcuda;

// Problem constants
#define B_    128
#define D_    2048
#define C_    16522
#define CP    16640          // padded logits stride: covers 130*128 tile stores
#define KNN_  6
#define BM    128
#define KC    32             // f32 K-elements per pipeline chunk
#define LDA   40             // KC + 8 pad (conflict-free ldmatrix)
#define NCHUNK (D_ / KC)     // 64
#define NTILE  130           // ceil(C_/128)

static __device__ float g_logits[B_ * CP];   // ~8.5 MB scratch
static __device__ float g_rowloss[B_];

// SMEM: 2 stages x {A, B}, each 128 x LDA fp16 -> 40960 B
struct Smem {
    __half A[2][BM * LDA];
    __half Bm[2][BM * LDA];
};
#define SMEM_DYN (sizeof(Smem))

// ---------------------------------------------------------------------------
// Fused kernel: single-pass fp16 HMMA GEMM (logits = X·Emᵀ, x20 applied later)
// + fused em -> out copy. One CTA per 128-row em tile.
// A = em tile (M=128 rows), B = X (N=128 batch), K = 2048, f32 accumulate.
// ---------------------------------------------------------------------------
__global__ __launch_bounds__(256, 1) void gemm_fused(const float* __restrict__ X,
                                                     const float* __restrict__ Em,
                                                     float* __restrict__ out1) {
    extern __shared__ char smraw[];
    Smem* sm = (Smem*)smraw;

    const int tid = threadIdx.x;
    const int wid = tid >> 5;
    const int c0  = blockIdx.x * BM;
    const int wm  = (wid & 3) * 32;   // warp M origin (em rows)
    const int wn  = (wid >> 2) * 64;  // warp N origin (batch)

    wmma::fragment<wmma::accumulator, 16, 16, 16, float> acc[2][4];
    #pragma unroll
    for (int i = 0; i < 2; i++)
        #pragma unroll
        for (int j = 0; j < 4; j++) wmma::fill_fragment(acc[i][j], 0.0f);

    float4 pf[8];   // prefetch: 8 float4 = 32 f32 per thread per chunk

    // global -> registers for one K-chunk (A tile rows + X rows)
    auto ldchunk = [&](int chunk) {
        const int k0 = chunk * KC;
        #pragma unroll
        for (int t = 0; t < 8; t++) {
            const int g   = tid + t * 256;     // 0..2047
            const int mat = g >> 10;           // 0 = A(em), 1 = B(X)
            const int idx = g & 1023;
            const int row = idx >> 3;          // 0..127
            const int q   = idx & 7;           // quad of 4 floats
            if (mat == 0) {
                const int c = c0 + row;
                if (c < C_)
                    pf[t] = *(const float4*)(Em + (long long)c * D_ + k0 + q * 4);
                else
                    pf[t] = make_float4(0.f, 0.f, 0.f, 0.f);
            } else {
                pf[t] = *(const float4*)(X + (long long)row * D_ + k0 + q * 4);
            }
        }
    };

    // registers -> smem fp16 + fused em copy to out
    auto stchunk = [&](int chunk, int st) {
        const int k0 = chunk * KC;
        #pragma unroll
        for (int t = 0; t < 8; t++) {
            const int g   = tid + t * 256;
            const int mat = g >> 10;
            const int idx = g & 1023;
            const int row = idx >> 3;
            const int q   = idx & 7;
            float4 f = pf[t];
            __half2 h0 = __float22half2_rn(make_float2(f.x, f.y));
            __half2 h1 = __float22half2_rn(make_float2(f.z, f.w));
            __half* hb = mat ? sm->Bm[st] : sm->A[st];
            const int so = row * LDA + q * 4;
            *(__half2*)(hb + so)     = h0;
            *(__half2*)(hb + so + 2) = h1;
            if (mat == 0 && c0 + row < C_) {   // fused em -> out copy (4B-aligned dst)
                float* o = out1 + (long long)(c0 + row) * D_ + k0 + q * 4;
                o[0] = f.x; o[1] = f.y; o[2] = f.z; o[3] = f.w;
            }
        }
    };

    ldchunk(0);
    stchunk(0, 0);
    __syncthreads();

    for (int s = 0; s < NCHUNK; s++) {
        const int st = s & 1;
        if (s + 1 < NCHUNK) ldchunk(s + 1);   // overlap gmem latency with MMA

        #pragma unroll
        for (int kk = 0; kk < KC; kk += 16) {
            wmma::fragment<wmma::matrix_a, 16, 16, 16, __half, wmma::row_major> af[2];
            wmma::fragment<wmma::matrix_b, 16, 16, 16, __half, wmma::col_major> bf[4];
            #pragma unroll
            for (int i = 0; i < 2; i++)
                wmma::load_matrix_sync(af[i], sm->A[st] + (wm + i * 16) * LDA + kk, LDA);
            #pragma unroll
            for (int j = 0; j < 4; j++)
                wmma::load_matrix_sync(bf[j], sm->Bm[st] + (wn + j * 16) * LDA + kk, LDA);
            #pragma unroll
            for (int i = 0; i < 2; i++)
                #pragma unroll
                for (int j = 0; j < 4; j++)
                    wmma::mma_sync(acc[i][j], af[i], bf[j], acc[i][j]);
        }
        __syncthreads();
        if (s + 1 < NCHUNK) {
            stchunk(s + 1, st ^ 1);
            __syncthreads();
        }
    }

    // store: D(m=c-local, n=batch) -> g_logits[n*CP + c0+m] (col-major store)
    #pragma unroll
    for (int i = 0; i < 2; i++)
        #pragma unroll
        for (int j = 0; j < 4; j++) {
            float* p = g_logits + (long long)(wn + j * 16) * CP + c0 + wm + i * 16;
            wmma::store_matrix_sync(p, acc[i][j], CP, wmma::mem_col_major);
        }
}

// ---------------------------------------------------------------------------
// Per-row logsumexp + top-6 + row loss. One block per B-row; x20 at load.
// ---------------------------------------------------------------------------
__global__ __launch_bounds__(256) void row_reduce_kernel(const int* __restrict__ label) {
    const int b   = blockIdx.x;
    const int tid = threadIdx.x;
    const float* row = &g_logits[b * CP];

    float m = -INFINITY, s = 0.f;
    float tv[KNN_];
    int   ti[KNN_];
    #pragma unroll
    for (int j = 0; j < KNN_; j++) { tv[j] = -INFINITY; ti[j] = -1; }

    for (int c = tid; c < C_; c += 256) {
        float v = row[c] * 20.0f;
        if (v > m) { s = s * __expf(m - v) + 1.f; m = v; }
        else       { s += __expf(v - m); }
        if (v > tv[KNN_ - 1]) {
            int p = KNN_ - 1;
            while (p > 0 && v > tv[p - 1]) { tv[p] = tv[p - 1]; ti[p] = ti[p - 1]; p--; }
            tv[p] = v; ti[p] = c;
        }
    }

    __shared__ float sm[256], ss[256];
    __shared__ float cv[256 * KNN_];
    __shared__ int   ci[256 * KNN_];
    __shared__ float rv[256];
    __shared__ int   ri[256];
    __shared__ float out_tv[KNN_];
    __shared__ int   out_ti[KNN_];

    sm[tid] = m; ss[tid] = s;
    #pragma unroll
    for (int j = 0; j < KNN_; j++) { cv[tid * KNN_ + j] = tv[j]; ci[tid * KNN_ + j] = ti[j]; }
    __syncthreads();

    for (int off = 128; off > 0; off >>= 1) {
        if (tid < off) {
            float m2 = sm[tid + off], s2 = ss[tid + off];
            float m1 = sm[tid],       s1 = ss[tid];
            float mm = fmaxf(m1, m2);
            ss[tid] = s1 * __expf(m1 - mm) + s2 * __expf(m2 - mm);
            sm[tid] = mm;
        }
        __syncthreads();
    }

    for (int r = 0; r < KNN_; r++) {
        float bm = -INFINITY; int bi = -1;
        #pragma unroll
        for (int j = 0; j < KNN_; j++) {
            float v = cv[tid * KNN_ + j];
            if (v > bm) { bm = v; bi = tid * KNN_ + j; }
        }
        rv[tid] = bm; ri[tid] = bi;
        __syncthreads();
        for (int off = 128; off > 0; off >>= 1) {
            if (tid < off && rv[tid + off] > rv[tid]) {
                rv[tid] = rv[tid + off]; ri[tid] = ri[tid + off];
            }
            __syncthreads();
        }
        if (tid == 0) {
            out_tv[r] = rv[0];
            out_ti[r] = ci[ri[0]];
            cv[ri[0]] = -INFINITY;
        }
        __syncthreads();
    }

    if (tid == 0) {
        float LSE  = sm[0] + logf(ss[0]);
        int   y    = label[b];
        float vlab = row[y] * 20.0f;
        float sum2 = 0.f;
        int   in   = 0;
        #pragma unroll
        for (int j = 0; j < KNN_; j++) {
            sum2 += (LSE - out_tv[j]);
            if (out_ti[j] == y) in = 1;
        }
        float ll = LSE - vlab;
        g_rowloss[b] = 2.f * sum2 + (3.f - 2.f * (float)in) * ll;
    }
}

// ---------------------------------------------------------------------------
// EMA memory-bank update + (block 128) loss finalize.
// One block per sample; only chain heads work; labels staged in smem.
// ---------------------------------------------------------------------------
__global__ __launch_bounds__(256) void update_finalize(const float* __restrict__ X,
                                                       const int* __restrict__ label,
                                                       const float* __restrict__ em,
                                                       float* __restrict__ em_out,
                                                       const int* __restrict__ epoch_p,
                                                       float* __restrict__ loss_out) {
    const int tid = threadIdx.x;

    if (blockIdx.x == B_) {      // finalize block: mean of row losses -> loss_out
        __shared__ float sh[128];
        if (tid < 128) sh[tid] = g_rowloss[tid];
        __syncthreads();
        for (int off = 64; off > 0; off >>= 1) {
            if (tid < off) sh[tid] += sh[tid + off];
            __syncthreads();
        }
        if (tid == 0) loss_out[0] = sh[0] / (float)B_;
        return;
    }

    __shared__ int lab[B_];
    if (tid < B_) lab[tid] = label[tid];
    __syncthreads();

    const int b = blockIdx.x;
    const int y = lab[b];
    bool head = true;
    for (int j = 0; j < b; j++)
        if (lab[j] == y) { head = false; break; }
    if (!head) return;

    const float alpha = 0.01f * (float)epoch_p[0];
    const int lane = tid & 31, wid = tid >> 5;

    float r[8];
    #pragma unroll
    for (int k = 0; k < 8; k++) r[k] = em[(long long)y * D_ + k * 256 + tid];

    __shared__ float red[8];

    for (int i = b; i < B_; i++) {
        if (lab[i] != y) continue;
        float sq = 0.f;
        #pragma unroll
        for (int k = 0; k < 8; k++) {
            r[k] = alpha * r[k] + (1.f - alpha) * X[i * D_ + k * 256 + tid];
            sq = fmaf(r[k], r[k], sq);
        }
        #pragma unroll
        for (int o = 16; o > 0; o >>= 1) sq += __shfl_xor_sync(0xffffffffu, sq, o);
        if (lane == 0) red[wid] = sq;
        __syncthreads();
        if (tid == 0) {
            float tot = 0.f;
            #pragma unroll
            for (int w = 0; w < 8; w++) tot += red[w];
            red[0] = tot;
        }
        __syncthreads();
        float inv = 1.f / sqrtf(red[0]);
        __syncthreads();
        #pragma unroll
        for (int k = 0; k < 8; k++) r[k] *= inv;
    }

    #pragma unroll
    for (int k = 0; k < 8; k++) em_out[(long long)y * D_ + k * 256 + tid] = r[k];
}

// ---------------------------------------------------------------------------
// Launch
// ---------------------------------------------------------------------------
extern "C" void kernel_launch(void* const* d_in, const int* in_sizes, int n_in,
                              void* d_out, int out_size) {
    const float* X     = (const float*)d_in[0];  // [128, 2048] f32
    const int*   label = (const int*)  d_in[1];  // [128] i32
    const float* Em    = (const float*)d_in[2];  // [16522, 2048] f32
    const int*   epoch = (const int*)  d_in[3];  // scalar

    float* out = (float*)d_out;                  // [0]=loss, [1..]=em_new

    cudaFuncSetAttribute(gemm_fused, cudaFuncAttributeMaxDynamicSharedMemorySize, SMEM_DYN);

    gemm_fused       <<<NTILE, 256, SMEM_DYN>>>(X, Em, out + 1);
    row_reduce_kernel<<<B_, 256>>>(label);
    update_finalize  <<<B_ + 1, 256>>>(X, label, Em, out + 1, epoch, out);
}